// round 6
// baseline (speedup 1.0000x reference)
#include <cuda_runtime.h>

// LineGraphic2d: distance-field line segment on 8192x8192 fp32 canvas.
// Store-bound (256 MB out). Correctness: emulate XLA-GPU codegen literally:
//   - NO fma contraction (XLA emits fmul/fadd without contract flags)
//   - fp32 division via div.full.f32 (XLA GPU's non-IEEE ~2ulp divide) -- this
//     is the op whose error (amplified ~8000x through ey = ry - t*dy) explains
//     the single contour-pixel flip that exact/IEEE arithmetic cannot reproduce.
//   - sqrt.rn

#define H 8192
#define W 8192
#define WIDTH_PX 3.0f
#define EPSILON_F 0.001f

__device__ __forceinline__ float div_full(float a, float b) {
    float r;
    asm("div.full.f32 %0, %1, %2;" : "=f"(r) : "f"(a), "f"(b));
    return r;
}

__global__ void __launch_bounds__(256) line2d_kernel(
    const float* __restrict__ kp, float4* __restrict__ out)
{
    const int idx = blockIdx.x * blockDim.x + threadIdx.x;  // one float4 = 4 pixels
    const int pix = idx << 2;
    const int y = pix >> 13;          // / 8192
    const int x = pix & (W - 1);      // % 8192

    // key_points [2,2]: rows=(p0,p1), cols=(y,x). x8192 is exact (power of two),
    // so p0, d match the reference's fp32 scalars bit-for-bit.
    const float4 k = *reinterpret_cast<const float4*>(kp);
    const float p0y = __fmul_rn(k.x, (float)H);
    const float p0x = __fmul_rn(k.y, (float)W);
    const float dy  = __fsub_rn(__fmul_rn(k.z, (float)H), p0y);
    const float dx  = __fsub_rn(__fmul_rn(k.w, (float)W), p0x);
    // len2 = d0*d0 + d1*d1  (unfused, separately rounded)
    const float len2 = __fadd_rn(__fmul_rn(dy, dy), __fmul_rn(dx, dx));
    // max_distance = norm([8192,8192]) in fp32 (sums exact, one sqrt rounding)
    const float maxd = __fsqrt_rn(134217728.0f);

    const float ry = __fsub_rn((float)y, p0y);
    const float ry_dy = __fmul_rn(ry, dy);   // ref's ry*d[0] (per-row broadcast)

    float4 o;
    float* op = &o.x;
    #pragma unroll
    for (int j = 0; j < 4; ++j) {
        const float rx = __fsub_rn((float)(x + j), p0x);
        // t = clip((ry*d0 + rx*d1) / len2, 0, 1) -- div.full.f32, unfused dot
        float t = div_full(__fadd_rn(ry_dy, __fmul_rn(rx, dx)), len2);
        t = fminf(fmaxf(t, 0.0f), 1.0f);
        // e = r - t*d  (unfused: mul then sub)
        const float ey = __fsub_rn(ry, __fmul_rn(t, dy));
        const float ex = __fsub_rn(rx, __fmul_rn(t, dx));
        const float e2 = fmaxf(__fadd_rn(__fmul_rn(ey, ey), __fmul_rn(ex, ex)), 1e-12f);
        const float dist = __fsqrt_rn(e2);
        // value = 1 - (dist/maxd + eps); AA_FACTOR=1 -> pow is identity
        const float v = __fsub_rn(1.0f, __fadd_rn(div_full(dist, maxd), EPSILON_F));
        op[j] = (dist < WIDTH_PX) ? v : 0.0f;
    }
    out[idx] = o;
}

extern "C" void kernel_launch(void* const* d_in, const int* in_sizes, int n_in,
                              void* d_out, int out_size)
{
    const float* kp = (const float*)d_in[0];
    float4* out = (float4*)d_out;
    const int n_vec4 = (H * W) / 4;          // 16,777,216 float4 stores
    const int threads = 256;
    const int blocks = n_vec4 / threads;     // 65,536 blocks
    line2d_kernel<<<blocks, threads>>>(kp, out);
}